// round 7
// baseline (speedup 1.0000x reference)
#include <cuda_runtime.h>
#include <cuda_bf16.h>
#include <math.h>

// Problem constants
#define B 4
#define T 512
#define C 256
#define C2 512
#define HEADS 4
#define MAXOFF 2

#define TI 32          // i-tile per block (rep)
#define TJ 64          // j-tile per block (rep)
#define NJT (T / TJ)   // 8 j-tiles
#define CK 128         // c chunk (rep)

typedef unsigned long long u64;

// Scratch (allocation-free: device globals)
__device__ float g_subj[B * T * C];
__device__ float g_obj[B * T * C];
__device__ float g_part[B * T * NJT * HEADS];   // partial exp-sums per j-tile
__device__ float g_swow[2 * B * T * HEADS];     // Sw (rows 0..2047), Ow (rows 2048..4095)

// packed f32x2 helpers
static __device__ __forceinline__ u64 fma2(u64 a, u64 b, u64 c) {
    u64 r; asm("fma.rn.f32x2 %0, %1, %2, %3;" : "=l"(r) : "l"(a), "l"(b), "l"(c)); return r;
}
static __device__ __forceinline__ float2 unpack2(u64 v) {
    float2 r; asm("mov.b64 {%0, %1}, %2;" : "=f"(r.x), "=f"(r.y) : "l"(v)); return r;
}
// packed elementwise min of two f32x2 (FMNMX on ALU pipe)
static __device__ __forceinline__ u64 fmin2(u64 a, u64 b) {
    u64 r;
    asm("{\n\t"
        ".reg .f32 al, ah, bl, bh, cl, ch;\n\t"
        "mov.b64 {al, ah}, %1;\n\t"
        "mov.b64 {bl, bh}, %2;\n\t"
        "min.f32 cl, al, bl;\n\t"
        "min.f32 ch, ah, bh;\n\t"
        "mov.b64 %0, {cl, ch};\n\t"
        "}" : "=l"(r) : "l"(a), "l"(b));
    return r;
}

// ---------------------------------------------------------------------------
// Kernel 1: max-pool along channel (window 5, pad 2) + concat -> x_new
// ---------------------------------------------------------------------------
__global__ void pool_concat_kernel(const float* __restrict__ x,
                                   float* __restrict__ xnew) {
    int idx = blockIdx.x * 256 + threadIdx.x;
    if (idx >= B * T * C2) return;
    int cc = idx & (C2 - 1);
    int bt = idx >> 9;
    const float* xr = x + bt * C;
    float v;
    if (cc < C) {
        int lo = cc - MAXOFF; if (lo < 0) lo = 0;
        int hi = cc + MAXOFF; if (hi > C - 1) hi = C - 1;
        v = -INFINITY;
        #pragma unroll 5
        for (int c = lo; c <= hi; c++) v = fmaxf(v, xr[c]);
    } else {
        v = xr[cc - C];
    }
    xnew[idx] = v;
}

// ---------------------------------------------------------------------------
// Kernel 2: both projection GEMMs (scalar, at fp32 roofline ~30us)
// ---------------------------------------------------------------------------
__global__ void gemm_kernel(const float* __restrict__ A,
                            const float* __restrict__ W0,
                            const float* __restrict__ b0,
                            const float* __restrict__ W1,
                            const float* __restrict__ b1,
                            float* __restrict__ out0,
                            float* __restrict__ out1) {
    const int N = C;
    const int K = C2;

    const float* W    = blockIdx.z ? W1 : W0;
    const float* bias = blockIdx.z ? b1 : b0;
    float* out        = blockIdx.z ? out1 : out0;

    __shared__ float As[16][68];
    __shared__ float Ws[16][64];

    int tid = threadIdx.x;
    int tx = tid & 15;
    int ty = tid >> 4;
    int bm = blockIdx.y * 64;
    int bn = blockIdx.x * 64;

    float acc[4][4];
    #pragma unroll
    for (int i = 0; i < 4; i++)
        #pragma unroll
        for (int j = 0; j < 4; j++) acc[i][j] = 0.0f;

    for (int k0 = 0; k0 < K; k0 += 16) {
        #pragma unroll
        for (int l = 0; l < 4; l++) {
            int idx = tid + l * 256;
            int m = idx >> 4, ka = idx & 15;
            As[ka][m] = A[(bm + m) * K + k0 + ka];
            int n2 = idx & 63, kw = idx >> 6;
            Ws[kw][n2] = W[(k0 + kw) * N + bn + n2];
        }
        __syncthreads();
        #pragma unroll
        for (int k = 0; k < 16; k++) {
            float a[4], w[4];
            #pragma unroll
            for (int i = 0; i < 4; i++) a[i] = As[k][ty * 4 + i];
            float4 wv = *(const float4*)&Ws[k][tx * 4];
            w[0] = wv.x; w[1] = wv.y; w[2] = wv.z; w[3] = wv.w;
            #pragma unroll
            for (int i = 0; i < 4; i++)
                #pragma unroll
                for (int j = 0; j < 4; j++)
                    acc[i][j] += a[i] * w[j];
        }
        __syncthreads();
    }

    float4 bv = *(const float4*)&bias[bn + tx * 4];
    #pragma unroll
    for (int i = 0; i < 4; i++) {
        float4 o;
        o.x = acc[i][0] + bv.x;
        o.y = acc[i][1] + bv.y;
        o.z = acc[i][2] + bv.z;
        o.w = acc[i][3] + bv.w;
        *(float4*)&out[(bm + ty * 4 + i) * N + bn + tx * 4] = o;
    }
}

// ---------------------------------------------------------------------------
// Kernel 2b: Sw[j,h] = subj[j,:] @ W_t  and  Ow[i,h] = obj[i,:] @ W_t.
// One warp per row; 4096 rows total.
// ---------------------------------------------------------------------------
__global__ void __launch_bounds__(128)
swow_kernel(const float* __restrict__ subj,
            const float* __restrict__ obj,
            const float* __restrict__ W_t,
            float* __restrict__ swow) {
    int gw = (blockIdx.x * 128 + threadIdx.x) >> 5;   // 0..4095
    int lane = threadIdx.x & 31;
    const float* src = (gw < B * T) ? subj : obj;
    int row = gw & (B * T - 1);

    float4 a = make_float4(0.f, 0.f, 0.f, 0.f);
    const float4* wt4 = (const float4*)W_t;
    #pragma unroll
    for (int c = lane; c < C; c += 32) {
        float s = src[row * C + c];
        float4 w = wt4[c];
        a.x += s * w.x; a.y += s * w.y; a.z += s * w.z; a.w += s * w.w;
    }
    #pragma unroll
    for (int m = 16; m >= 1; m >>= 1) {
        a.x += __shfl_xor_sync(0xffffffffu, a.x, m);
        a.y += __shfl_xor_sync(0xffffffffu, a.y, m);
        a.z += __shfl_xor_sync(0xffffffffu, a.z, m);
        a.w += __shfl_xor_sync(0xffffffffu, a.w, m);
    }
    if (lane == 0) ((float4*)swow)[gw] = a;
}

// ---------------------------------------------------------------------------
// Kernel 3a: e = exp(relu(rep)) for a 32i x 64j tile, via the min-trick:
// rep = Sw[j] + Ow[i] + b - 2*sum_c min(s,o)*w   (w_sh holds -2*W_t)
// 128 threads = 16 tx (j, stride-16) x 8 ty (i, stride-8); 4i x 4j microtile.
// ---------------------------------------------------------------------------
__global__ void __launch_bounds__(128)
rep_exp_kernel(const float* __restrict__ subj,
               const float* __restrict__ obj,
               const float* __restrict__ W_t,
               const float* __restrict__ b_t,
               const float* __restrict__ swow,
               float* __restrict__ attn,
               float* __restrict__ part) {
    __shared__ float s_sh[TJ * CK];     // [jrow][c], swizzled (32KB)
    __shared__ float o_sh[TI * CK];     // [irow][c], swizzled (16KB)
    __shared__ float w_sh[HEADS * C];   // [h][c] = -2*W_t (4KB)

    const int tid = threadIdx.x;
    const int tx = tid & 15;           // j: j0 + tx + 16q
    const int ty = tid >> 4;           // i: i0 + ty + 8p   (0..7)
    const int jt = blockIdx.x;
    const int j0 = jt * TJ;
    const int i0 = blockIdx.y * TI;
    const int b  = blockIdx.z;

    // Load W_t transposed & scaled: w_sh[h][c] = -2 * W_t[c*4+h]
    #pragma unroll
    for (int c = tid; c < C; c += 128) {
        float4 wv = *(const float4*)&W_t[c * 4];
        w_sh[0 * C + c] = -2.0f * wv.x;
        w_sh[1 * C + c] = -2.0f * wv.y;
        w_sh[2 * C + c] = -2.0f * wv.z;
        w_sh[3 * C + c] = -2.0f * wv.w;
    }

    u64 acc[4][4][4];
    #pragma unroll
    for (int p = 0; p < 4; p++)
        #pragma unroll
        for (int q = 0; q < 4; q++)
            #pragma unroll
            for (int h = 0; h < 4; h++) acc[p][q][h] = 0ULL;

    const int swj = tx & 7;
    const float* sp[4];
    const float* op[4];
    #pragma unroll
    for (int q = 0; q < 4; q++) sp[q] = s_sh + (tx + 16 * q) * CK;
    #pragma unroll
    for (int p = 0; p < 4; p++) op[p] = o_sh + (ty + 8 * p) * CK;

    for (int ck = 0; ck < C / CK; ck++) {
        const int cbase = ck * CK;
        #pragma unroll
        for (int l = 0; l < 16; l++) {
            int t = tid + l * 128;
            int row = t >> 5;          // 0..63
            int ccg = t & 31;
            int phys = (ccg ^ (row & 7)) << 2;
            float4 sv = *(const float4*)&subj[(b * T + j0 + row) * C + cbase + ccg * 4];
            *(float4*)&s_sh[row * CK + phys] = sv;
        }
        #pragma unroll
        for (int l = 0; l < 8; l++) {
            int t = tid + l * 128;
            int row = t >> 5;          // 0..31
            int ccg = t & 31;
            int phys = (ccg ^ (row & 7)) << 2;
            float4 ov = *(const float4*)&obj[(b * T + i0 + row) * C + cbase + ccg * 4];
            *(float4*)&o_sh[row * CK + phys] = ov;
        }
        __syncthreads();

        const float* wp0 = w_sh + 0 * C + cbase;
        const float* wp1 = w_sh + 1 * C + cbase;
        const float* wp2 = w_sh + 2 * C + cbase;
        const float* wp3 = w_sh + 3 * C + cbase;

        #pragma unroll 1
        for (int g = 0; g < CK / 4; g++) {
            const int gs = ((g ^ swj) << 2);
            const int gi = ((g ^ ty) << 2);
            ulonglong2 S[4], P[4], Wv[4];
            #pragma unroll
            for (int q = 0; q < 4; q++) S[q] = *(const ulonglong2*)(sp[q] + gs);
            #pragma unroll
            for (int p = 0; p < 4; p++) P[p] = *(const ulonglong2*)(op[p] + gi);
            Wv[0] = *(const ulonglong2*)(wp0 + g * 4);
            Wv[1] = *(const ulonglong2*)(wp1 + g * 4);
            Wv[2] = *(const ulonglong2*)(wp2 + g * 4);
            Wv[3] = *(const ulonglong2*)(wp3 + g * 4);

            #pragma unroll
            for (int p = 0; p < 4; p++) {
                #pragma unroll
                for (int q = 0; q < 4; q++) {
                    u64 m0 = fmin2(S[q].x, P[p].x);
                    acc[p][q][0] = fma2(m0, Wv[0].x, acc[p][q][0]);
                    acc[p][q][1] = fma2(m0, Wv[1].x, acc[p][q][1]);
                    acc[p][q][2] = fma2(m0, Wv[2].x, acc[p][q][2]);
                    acc[p][q][3] = fma2(m0, Wv[3].x, acc[p][q][3]);
                    u64 m1 = fmin2(S[q].y, P[p].y);
                    acc[p][q][0] = fma2(m1, Wv[0].y, acc[p][q][0]);
                    acc[p][q][1] = fma2(m1, Wv[1].y, acc[p][q][1]);
                    acc[p][q][2] = fma2(m1, Wv[2].y, acc[p][q][2]);
                    acc[p][q][3] = fma2(m1, Wv[3].y, acc[p][q][3]);
                }
            }
        }
        __syncthreads();
    }

    // Epilogue: z = relu(Sw[j] + Ow[i] + b + acc), e = exp(z)
    const float4 btv = *(const float4*)b_t;
    const float4* sw4 = (const float4*)swow;              // rows 0..B*T-1
    const float4* ow4 = (const float4*)swow + B * T;      // rows B*T..

    float4 owv[4];
    #pragma unroll
    for (int p = 0; p < 4; p++) owv[p] = ow4[b * T + i0 + ty + 8 * p];

    #pragma unroll
    for (int p = 0; p < 4; p++) {
        int i = i0 + ty + 8 * p;
        float4 ps = make_float4(0.f, 0.f, 0.f, 0.f);
        float base_x = owv[p].x + btv.x;
        float base_y = owv[p].y + btv.y;
        float base_z = owv[p].z + btv.z;
        float base_w = owv[p].w + btv.w;
        #pragma unroll
        for (int q = 0; q < 4; q++) {
            int j = j0 + tx + 16 * q;
            float4 swv = sw4[b * T + j];
            float2 f0 = unpack2(acc[p][q][0]);
            float2 f1 = unpack2(acc[p][q][1]);
            float2 f2 = unpack2(acc[p][q][2]);
            float2 f3 = unpack2(acc[p][q][3]);
            float4 ev;
            ev.x = __expf(fmaxf(f0.x + f0.y + swv.x + base_x, 0.0f));
            ev.y = __expf(fmaxf(f1.x + f1.y + swv.y + base_y, 0.0f));
            ev.z = __expf(fmaxf(f2.x + f2.y + swv.z + base_z, 0.0f));
            ev.w = __expf(fmaxf(f3.x + f3.y + swv.w + base_w, 0.0f));
            *(float4*)&attn[(((size_t)(b * T + i)) * T + j) * HEADS] = ev;
            ps.x += ev.x; ps.y += ev.y; ps.z += ev.z; ps.w += ev.w;
        }
        #pragma unroll
        for (int m = 8; m >= 1; m >>= 1) {
            ps.x += __shfl_xor_sync(0xffffffffu, ps.x, m);
            ps.y += __shfl_xor_sync(0xffffffffu, ps.y, m);
            ps.z += __shfl_xor_sync(0xffffffffu, ps.z, m);
            ps.w += __shfl_xor_sync(0xffffffffu, ps.w, m);
        }
        if (tx == 0)
            *(float4*)&part[((size_t)(b * T + i) * NJT + jt) * HEADS] = ps;
    }
}

// ---------------------------------------------------------------------------
// Kernel 3b: fused denominator (one-warp shfl reduce) + normalize + mask.
// ---------------------------------------------------------------------------
__global__ void __launch_bounds__(128)
normalize_kernel(const float* __restrict__ part,
                 const int* __restrict__ mask,
                 float* __restrict__ attn) {
    __shared__ float sinv[4];
    const int bi = blockIdx.x;         // b*T + i
    const int tid = threadIdx.x;

    if (tid < 32) {
        float v = part[bi * (NJT * HEADS) + tid];   // 32 contiguous floats
        v += __shfl_xor_sync(0xffffffffu, v, 4);
        v += __shfl_xor_sync(0xffffffffu, v, 8);
        v += __shfl_xor_sync(0xffffffffu, v, 16);
        if (tid < 4) sinv[tid] = 1.0f / v;
    }
    __syncthreads();

    const float4 iv = make_float4(sinv[0], sinv[1], sinv[2], sinv[3]);
    const int mi = mask[bi];
    const int b = bi >> 9;
    float4* arow = (float4*)attn + (size_t)bi * T;

    #pragma unroll
    for (int r = 0; r < 4; r++) {
        int j = tid + r * 128;
        float4 v = arow[j];
        int mj = mask[b * T + j];
        float kill = (mi && mj) ? 0.0f : 1.0f;
        v.x *= iv.x * kill;
        v.y *= iv.y * kill;
        v.z *= iv.z * kill;
        v.w *= iv.w * kill;
        arow[j] = v;
    }
}

// ---------------------------------------------------------------------------
extern "C" void kernel_launch(void* const* d_in, const int* in_sizes, int n_in,
                              void* d_out, int out_size) {
    const float* x      = (const float*)d_in[0];
    const float* W_subj = (const float*)d_in[1];
    const float* b_subj = (const float*)d_in[2];
    const float* W_obj  = (const float*)d_in[3];
    const float* b_obj  = (const float*)d_in[4];
    const float* W_t    = (const float*)d_in[5];
    const float* b_t    = (const float*)d_in[6];
    const int*   mask   = (const int*)d_in[7];

    float* out   = (float*)d_out;
    float* xnew  = out;                          // (B,T,2C)
    float* attn  = out + (size_t)B * T * C2;     // (B,T,T,HEADS)

    float *subj, *obj, *part, *swow;
    cudaGetSymbolAddress((void**)&subj, g_subj);
    cudaGetSymbolAddress((void**)&obj, g_obj);
    cudaGetSymbolAddress((void**)&part, g_part);
    cudaGetSymbolAddress((void**)&swow, g_swow);

    pool_concat_kernel<<<(B * T * C2 + 255) / 256, 256>>>(x, xnew);

    dim3 gg(C / 64, (B * T) / 64, 2);   // (4, 32, 2)
    gemm_kernel<<<gg, 256>>>(xnew, W_subj, b_subj, W_obj, b_obj, subj, obj);

    swow_kernel<<<(2 * B * T) / 4, 128>>>(subj, obj, W_t, swow);

    dim3 ga(T / TJ, T / TI, B);         // (8, 16, 4) = 512 blocks
    rep_exp_kernel<<<ga, 128>>>(subj, obj, W_t, b_t, swow, attn, part);

    normalize_kernel<<<B * T, 128>>>(part, mask, attn);
}